// round 1
// baseline (speedup 1.0000x reference)
#include <cuda_runtime.h>

// Problem constants
#define B_    16
#define LL_   256
#define LP_   1024
#define HID_  128
#define H_    8
#define HD_   1024   // H*HID

// ---------------- scratch (static device memory; no allocation) ----------------
__device__ float g_l1[B_ * LL_ * HD_];
__device__ float g_l2[B_ * LL_ * HD_];
__device__ float g_p1[B_ * LP_ * HD_];
__device__ float g_p2[B_ * LP_ * HD_];
__device__ float g_att[(size_t)B_ * H_ * LL_ * LP_];      // energy -> att (in place)
__device__ float g_lig3[B_ * LL_ * HD_];
__device__ float g_prot3[B_ * LP_ * HD_];
__device__ float g_ligcat[B_ * LL_ * 2 * HID_];
__device__ float g_protcat[B_ * LP_ * 2 * HID_];

// ---------------- generic tiled GEMM ----------------
// C[M,N] = act( A @ B + bias )
//   TA: A stored [K,M] row-major (lda = row stride), else [M,K]
//   TB: B stored [N,K] row-major, else [K,N]
// Batched over blockIdx.z = b*8 + h with independent (batch, head) strides.
// All dims assumed exact multiples of tiles (true for this problem).
template <int BM, int BN, int BK, int TM, int TN, bool TA, bool TB, bool BIAS, bool RELU>
__global__ __launch_bounds__((BM / TM) * (BN / TN))
void gemm_k(const float* __restrict__ Ag, const float* __restrict__ Bg,
            const float* __restrict__ bias, float* __restrict__ Cg,
            int K, int lda, int ldb, int ldc,
            long sAb, long sAh, long sBb, long sBh, long sCb, long sCh)
{
    constexpr int THREADS = (BM / TM) * (BN / TN);
    __shared__ float As[BK][BM + 4];
    __shared__ float Bs[BK][BN + 4];

    const int z = blockIdx.z;
    const float* A = Ag + (size_t)(z >> 3) * sAb + (size_t)(z & 7) * sAh;
    const float* B = Bg + (size_t)(z >> 3) * sBb + (size_t)(z & 7) * sBh;
    float* C = Cg + (size_t)(z >> 3) * sCb + (size_t)(z & 7) * sCh;

    const int bm = blockIdx.y * BM;
    const int bn = blockIdx.x * BN;
    const int tid = threadIdx.x;
    const int tcol = tid % (BN / TN);
    const int trow = tid / (BN / TN);

    float acc[TM][TN] = {};

    for (int k0 = 0; k0 < K; k0 += BK) {
        // ---- load A tile -> As[k][m]
        {
            constexpr int NV = BM * BK / 4 / THREADS;
            if (!TA) {
#pragma unroll
                for (int i = 0; i < NV; i++) {
                    int idx = tid + i * THREADS;
                    int row = idx / (BK / 4);          // m
                    int col = (idx % (BK / 4)) * 4;    // k
                    float4 v = *(const float4*)(A + (size_t)(bm + row) * lda + (k0 + col));
                    As[col + 0][row] = v.x; As[col + 1][row] = v.y;
                    As[col + 2][row] = v.z; As[col + 3][row] = v.w;
                }
            } else {
#pragma unroll
                for (int i = 0; i < NV; i++) {
                    int idx = tid + i * THREADS;
                    int row = idx / (BM / 4);          // k
                    int col = (idx % (BM / 4)) * 4;    // m
                    *(float4*)&As[row][col] =
                        *(const float4*)(A + (size_t)(k0 + row) * lda + (bm + col));
                }
            }
        }
        // ---- load B tile -> Bs[k][n]
        {
            constexpr int NV = BN * BK / 4 / THREADS;
            if (!TB) {
#pragma unroll
                for (int i = 0; i < NV; i++) {
                    int idx = tid + i * THREADS;
                    int row = idx / (BN / 4);          // k
                    int col = (idx % (BN / 4)) * 4;    // n
                    *(float4*)&Bs[row][col] =
                        *(const float4*)(B + (size_t)(k0 + row) * ldb + (bn + col));
                }
            } else {
#pragma unroll
                for (int i = 0; i < NV; i++) {
                    int idx = tid + i * THREADS;
                    int row = idx / (BK / 4);          // n
                    int col = (idx % (BK / 4)) * 4;    // k
                    float4 v = *(const float4*)(B + (size_t)(bn + row) * ldb + (k0 + col));
                    Bs[col + 0][row] = v.x; Bs[col + 1][row] = v.y;
                    Bs[col + 2][row] = v.z; Bs[col + 3][row] = v.w;
                }
            }
        }
        __syncthreads();

#pragma unroll
        for (int k = 0; k < BK; k++) {
            float ar[TM], br[TN];
#pragma unroll
            for (int i = 0; i < TM; i += 4)
                *(float4*)&ar[i] = *(const float4*)&As[k][trow * TM + i];
#pragma unroll
            for (int j = 0; j < TN; j += 4)
                *(float4*)&br[j] = *(const float4*)&Bs[k][tcol * TN + j];
#pragma unroll
            for (int i = 0; i < TM; i++)
#pragma unroll
                for (int j = 0; j < TN; j++)
                    acc[i][j] = fmaf(ar[i], br[j], acc[i][j]);
        }
        __syncthreads();
    }

    // ---- epilogue
#pragma unroll
    for (int i = 0; i < TM; i++) {
        size_t row = (size_t)(bm + trow * TM + i);
#pragma unroll
        for (int j = 0; j < TN; j += 4) {
            int col = bn + tcol * TN + j;
            float4 v = make_float4(acc[i][j], acc[i][j + 1], acc[i][j + 2], acc[i][j + 3]);
            if (BIAS) {
                const float4 bv = *(const float4*)(bias + col);
                v.x += bv.x; v.y += bv.y; v.z += bv.z; v.w += bv.w;
            }
            if (RELU) {
                v.x = fmaxf(v.x, 0.f); v.y = fmaxf(v.y, 0.f);
                v.z = fmaxf(v.z, 0.f); v.w = fmaxf(v.w, 0.f);
            }
            *(float4*)(C + row * ldc + col) = v;
        }
    }
}

// ---------------- softmax (in place on energy buffer) ----------------
// att[b,h,l,:] = softmax( energy[b,h,l,:] * (1/sqrt(128)) * inter[b,0,l,:] )
__global__ void softmax_kernel(float* __restrict__ att, const float* __restrict__ inter)
{
    const float inv = 0.08838834764831845f;  // 1/sqrt(128)
    int idx = blockIdx.x;                    // (b*8+h)*256 + l
    int l = idx & (LL_ - 1);
    int b = idx >> 11;                       // / (H*LL)
    float* row = att + (size_t)idx * LP_;
    const float* irow = inter + ((size_t)b * LL_ + l) * LP_;
    int t = threadIdx.x;

    float v[4];
    float m = -3.402823466e38f;
#pragma unroll
    for (int i = 0; i < 4; i++) {
        int p = t + (i << 8);
        v[i] = row[p] * inv * irow[p];
        m = fmaxf(m, v[i]);
    }

    __shared__ float sm[8], ss[8];
#pragma unroll
    for (int o = 16; o; o >>= 1) m = fmaxf(m, __shfl_xor_sync(0xffffffffu, m, o));
    if ((t & 31) == 0) sm[t >> 5] = m;
    __syncthreads();
    m = sm[0];
#pragma unroll
    for (int w = 1; w < 8; w++) m = fmaxf(m, sm[w]);

    float s = 0.f;
#pragma unroll
    for (int i = 0; i < 4; i++) { v[i] = __expf(v[i] - m); s += v[i]; }
#pragma unroll
    for (int o = 16; o; o >>= 1) s += __shfl_xor_sync(0xffffffffu, s, o);
    if ((t & 31) == 0) ss[t >> 5] = s;
    __syncthreads();
    s = ss[0] + ss[1] + ss[2] + ss[3] + ss[4] + ss[5] + ss[6] + ss[7];
    float r = 1.0f / s;
#pragma unroll
    for (int i = 0; i < 4; i++) row[t + (i << 8)] = v[i] * r;
}

// ---------------- copy residual into concat buffer cols [128:256) ----------------
// src: [rows,128] contiguous, dst: [rows,256], writes cols 128..255
__global__ void copy_concat(const float4* __restrict__ src, float4* __restrict__ dst, int n4)
{
    int i = blockIdx.x * 256 + threadIdx.x;
    if (i < n4) {
        int r = i >> 5;       // row (32 float4 per src row)
        int c = i & 31;
        dst[(size_t)r * 64 + 32 + c] = src[i];
    }
}

// ---------------- launcher ----------------
extern "C" void kernel_launch(void* const* d_in, const int* in_sizes, int n_in,
                              void* d_out, int out_size)
{
    const float* ligand = (const float*)d_in[0];
    const float* prot   = (const float*)d_in[1];
    const float* inter  = (const float*)d_in[2];
    const float* Wl1 = (const float*)d_in[3];  const float* bl1 = (const float*)d_in[4];
    const float* Wl2 = (const float*)d_in[5];  const float* bl2 = (const float*)d_in[6];
    const float* Wp1 = (const float*)d_in[7];  const float* bp1 = (const float*)d_in[8];
    const float* Wp2 = (const float*)d_in[9];  const float* bp2 = (const float*)d_in[10];
    const float* W11 = (const float*)d_in[11]; const float* b11 = (const float*)d_in[12];
    const float* W12 = (const float*)d_in[13]; const float* b12 = (const float*)d_in[14];
    const float* W21 = (const float*)d_in[15]; const float* b21 = (const float*)d_in[16];
    const float* W22 = (const float*)d_in[17]; const float* b22 = (const float*)d_in[18];

    float* out_lig  = (float*)d_out;                       // [16,256,128]
    float* out_prot = out_lig + (size_t)B_ * LL_ * HID_;   // [16,1024,128]

    float *l1, *l2, *p1, *p2, *att, *lig3, *prot3, *lcat, *pcat;
    cudaGetSymbolAddress((void**)&l1, g_l1);
    cudaGetSymbolAddress((void**)&l2, g_l2);
    cudaGetSymbolAddress((void**)&p1, g_p1);
    cudaGetSymbolAddress((void**)&p2, g_p2);
    cudaGetSymbolAddress((void**)&att, g_att);
    cudaGetSymbolAddress((void**)&lig3, g_lig3);
    cudaGetSymbolAddress((void**)&prot3, g_prot3);
    cudaGetSymbolAddress((void**)&lcat, g_ligcat);
    cudaGetSymbolAddress((void**)&pcat, g_protcat);

    dim3 blk(256);

    // --- projections: relu(x @ W + b) ---
    // ligand: M=4096, N=1024, K=128
    gemm_k<128,128,8,8,8,false,false,true,true><<<dim3(8,32,1), blk>>>(
        ligand, Wl1, bl1, l1, 128, 128, 1024, 1024, 0,0,0,0,0,0);
    gemm_k<128,128,8,8,8,false,false,true,true><<<dim3(8,32,1), blk>>>(
        ligand, Wl2, bl2, l2, 128, 128, 1024, 1024, 0,0,0,0,0,0);
    // prot: M=16384, N=1024, K=128
    gemm_k<128,128,8,8,8,false,false,true,true><<<dim3(8,128,1), blk>>>(
        prot, Wp1, bp1, p1, 128, 128, 1024, 1024, 0,0,0,0,0,0);
    gemm_k<128,128,8,8,8,false,false,true,true><<<dim3(8,128,1), blk>>>(
        prot, Wp2, bp2, p2, 128, 128, 1024, 1024, 0,0,0,0,0,0);

    // --- energy[b,h] = l1_h @ p1_h^T : M=256, N=1024, K=128, TRANSB ---
    gemm_k<128,128,8,8,8,false,true,false,false><<<dim3(8,2,128), blk>>>(
        l1, p1, nullptr, att, 128, 1024, 1024, 1024,
        (long)LL_*HD_, 128, (long)LP_*HD_, 128,
        (long)H_*LL_*LP_, (long)LL_*LP_);

    // --- softmax (scale * inter gating), in place ---
    softmax_kernel<<<B_*H_*LL_, 256>>>(att, inter);

    // --- lig3[b,l,h*128+d] = att[b,h] @ p2_h : M=256, N=128, K=1024 ---
    gemm_k<128,128,8,8,8,false,false,false,false><<<dim3(1,2,128), blk>>>(
        att, p2, nullptr, lig3, 1024, 1024, 1024, 1024,
        (long)H_*LL_*LP_, (long)LL_*LP_, (long)LP_*HD_, 128,
        (long)LL_*HD_, 128);

    // --- prot3[b,p,h*128+d] = att[b,h]^T @ l2_h : M=1024, N=128, K=256, TRANSA ---
    gemm_k<128,128,8,8,8,true,false,false,false><<<dim3(1,8,128), blk>>>(
        att, l2, nullptr, prot3, 256, 1024, 1024, 1024,
        (long)H_*LL_*LP_, (long)LL_*LP_, (long)LL_*HD_, 128,
        (long)LP_*HD_, 128);

    // --- ligand branch: cat(lig3@W11+b11, ligand) -> relu(@W12+b12) ---
    gemm_k<64,64,16,4,4,false,false,true,false><<<dim3(2,64,1), blk>>>(
        lig3, W11, b11, lcat, 1024, 1024, 128, 256, 0,0,0,0,0,0);
    copy_concat<<<512, 256>>>((const float4*)ligand, (float4*)lcat, B_*LL_*32);
    gemm_k<64,64,16,4,4,false,false,true,true><<<dim3(2,64,1), blk>>>(
        lcat, W12, b12, out_lig, 256, 256, 128, 128, 0,0,0,0,0,0);

    // --- protein branch: cat(prot3@W21+b21, prot) -> relu(@W22+b22) ---
    gemm_k<128,128,8,8,8,false,false,true,false><<<dim3(1,128,1), blk>>>(
        prot3, W21, b21, pcat, 1024, 1024, 128, 256, 0,0,0,0,0,0);
    copy_concat<<<2048, 256>>>((const float4*)prot, (float4*)pcat, B_*LP_*32);
    gemm_k<128,128,8,8,8,false,false,true,true><<<dim3(1,128,1), blk>>>(
        pcat, W22, b22, out_prot, 256, 256, 128, 128, 0,0,0,0,0,0);
}

// round 2
// speedup vs baseline: 3.7875x; 3.7875x over previous
#include <cuda_runtime.h>

// Problem constants
#define B_    16
#define LL_   256
#define LP_   1024
#define HID_  128
#define H_    8
#define HD_   1024   // H*HID

// ---------------- scratch (static device memory; no allocation) ----------------
__device__ float g_l1[B_ * LL_ * HD_];
__device__ float g_l2[B_ * LL_ * HD_];
__device__ float g_p1[B_ * LP_ * HD_];
__device__ float g_p2[B_ * LP_ * HD_];
__device__ float g_att[(size_t)B_ * H_ * LL_ * LP_];      // energy -> att (in place)
__device__ float g_lig3[B_ * LL_ * HD_];
__device__ float g_prot3[B_ * LP_ * HD_];
__device__ float g_ligcat[B_ * LL_ * 2 * HID_];
__device__ float g_protcat[B_ * LP_ * 2 * HID_];

// ---------------- helpers ----------------
__device__ __forceinline__ unsigned tf32_of(float f) {
    unsigned r;
    asm("cvt.rna.tf32.f32 %0, %1;" : "=r"(r) : "f"(f));
    return r;
}

__device__ __forceinline__ void mma_tf32(float c[4], const unsigned a[4], const unsigned b[2]) {
    asm volatile(
        "mma.sync.aligned.m16n8k8.row.col.f32.tf32.tf32.f32 "
        "{%0,%1,%2,%3}, {%4,%5,%6,%7}, {%8,%9}, {%0,%1,%2,%3};"
        : "+f"(c[0]), "+f"(c[1]), "+f"(c[2]), "+f"(c[3])
        : "r"(a[0]), "r"(a[1]), "r"(a[2]), "r"(a[3]), "r"(b[0]), "r"(b[1]));
}

// ---------------- TF32 tensor-core GEMM ----------------
// C[M,N] = act( A @ B + bias )
//   TA: A stored [K,M] (lda = row stride), else [M,K]
//   TB: B stored [N,K], else [K,N]
// Batched over blockIdx.z = b*8 + h. M,N multiples of 128; K multiple of 16.
template <int BM, int BN, int BK, bool TA, bool TB, bool BIAS, bool RELU>
__global__ __launch_bounds__(256, 2)
void gemm_tc(const float* __restrict__ Ag, const float* __restrict__ Bg,
             const float* __restrict__ bias, float* __restrict__ Cg,
             int K, int lda, int ldb, int ldc,
             long sAb, long sAh, long sBb, long sBh, long sCb, long sCh)
{
    __shared__ unsigned As[2][BK][BM + 8];   // [k][m], stride 136 -> conflict-free frags
    __shared__ unsigned Bs[2][BK][BN + 8];   // [k][n]

    const int z = blockIdx.z;
    const float* A = Ag + (size_t)(z >> 3) * sAb + (size_t)(z & 7) * sAh;
    const float* B = Bg + (size_t)(z >> 3) * sBb + (size_t)(z & 7) * sBh;
    float* C = Cg + (size_t)(z >> 3) * sCb + (size_t)(z & 7) * sCh;

    const int tid  = threadIdx.x;
    const int lane = tid & 31;
    const int warp = tid >> 5;
    const int mw = warp & 1;         // 2 warp rows  (64 each)
    const int nw = warp >> 1;        // 4 warp cols  (32 each)
    const int g  = lane >> 2;        // groupID
    const int tg = lane & 3;         // thread in group
    const int bm = blockIdx.y * BM;
    const int bn = blockIdx.x * BN;

    // per-thread staging indices (2 float4 loads each for A and B)
    int aR[2], aC[2], bR[2], bC[2];
#pragma unroll
    for (int i = 0; i < 2; i++) {
        int idx = tid + i * 256;
        if (!TA) { aR[i] = idx / 4;  aC[i] = (idx % 4) * 4; }   // m, k
        else     { aR[i] = idx / 32; aC[i] = (idx % 32) * 4; }  // k, m
        if (!TB) { bR[i] = idx / 32; bC[i] = (idx % 32) * 4; }  // k, n
        else     { bR[i] = idx / 4;  bC[i] = (idx % 4) * 4; }   // n, k
    }

    float acc[4][4][4];
#pragma unroll
    for (int i = 0; i < 4; i++)
#pragma unroll
        for (int j = 0; j < 4; j++)
#pragma unroll
            for (int r = 0; r < 4; r++) acc[i][j][r] = 0.f;

    auto fetch = [&](int k0, float4* va, float4* vb) {
#pragma unroll
        for (int i = 0; i < 2; i++) {
            va[i] = TA ? *(const float4*)(A + (size_t)(k0 + aR[i]) * lda + bm + aC[i])
                       : *(const float4*)(A + (size_t)(bm + aR[i]) * lda + k0 + aC[i]);
            vb[i] = TB ? *(const float4*)(B + (size_t)(bn + bR[i]) * ldb + k0 + bC[i])
                       : *(const float4*)(B + (size_t)(k0 + bR[i]) * ldb + bn + bC[i]);
        }
    };
    auto stage = [&](int buf, const float4* va, const float4* vb) {
#pragma unroll
        for (int i = 0; i < 2; i++) {
            float fa[4] = {va[i].x, va[i].y, va[i].z, va[i].w};
            float fb[4] = {vb[i].x, vb[i].y, vb[i].z, vb[i].w};
            if (!TA) {
#pragma unroll
                for (int j = 0; j < 4; j++) As[buf][aC[i] + j][aR[i]] = tf32_of(fa[j]);
            } else {
#pragma unroll
                for (int j = 0; j < 4; j++) As[buf][aR[i]][aC[i] + j] = tf32_of(fa[j]);
            }
            if (!TB) {
#pragma unroll
                for (int j = 0; j < 4; j++) Bs[buf][bR[i]][bC[i] + j] = tf32_of(fb[j]);
            } else {
#pragma unroll
                for (int j = 0; j < 4; j++) Bs[buf][bC[i] + j][bR[i]] = tf32_of(fb[j]);
            }
        }
    };

    float4 va[2], vb[2];
    fetch(0, va, vb);
    stage(0, va, vb);
    __syncthreads();

    const int nk = K / BK;
    for (int t = 0; t < nk; t++) {
        const int buf = t & 1;
        float4 wa[2], wb[2];
        if (t + 1 < nk) fetch((t + 1) * BK, wa, wb);

#pragma unroll
        for (int ks = 0; ks < BK; ks += 8) {
            unsigned af[4][4], bf[4][2];
#pragma unroll
            for (int mt = 0; mt < 4; mt++) {
                int m0 = mw * 64 + mt * 16;
                af[mt][0] = As[buf][ks + tg][m0 + g];
                af[mt][1] = As[buf][ks + tg][m0 + g + 8];
                af[mt][2] = As[buf][ks + tg + 4][m0 + g];
                af[mt][3] = As[buf][ks + tg + 4][m0 + g + 8];
            }
#pragma unroll
            for (int nt = 0; nt < 4; nt++) {
                int n0 = nw * 32 + nt * 8;
                bf[nt][0] = Bs[buf][ks + tg][n0 + g];
                bf[nt][1] = Bs[buf][ks + tg + 4][n0 + g];
            }
#pragma unroll
            for (int mt = 0; mt < 4; mt++)
#pragma unroll
                for (int nt = 0; nt < 4; nt++)
                    mma_tf32(acc[mt][nt], af[mt], bf[nt]);
        }

        if (t + 1 < nk) stage(buf ^ 1, wa, wb);
        __syncthreads();
    }

    // ---- epilogue
#pragma unroll
    for (int mt = 0; mt < 4; mt++) {
#pragma unroll
        for (int nt = 0; nt < 4; nt++) {
            int row = bm + mw * 64 + mt * 16 + g;
            int col = bn + nw * 32 + nt * 8 + 2 * tg;
            float b0 = 0.f, b1 = 0.f;
            if (BIAS) { b0 = bias[col]; b1 = bias[col + 1]; }
            float x0 = acc[mt][nt][0] + b0;
            float x1 = acc[mt][nt][1] + b1;
            float x2 = acc[mt][nt][2] + b0;
            float x3 = acc[mt][nt][3] + b1;
            if (RELU) {
                x0 = fmaxf(x0, 0.f); x1 = fmaxf(x1, 0.f);
                x2 = fmaxf(x2, 0.f); x3 = fmaxf(x3, 0.f);
            }
            *(float2*)(C + (size_t)row * ldc + col) = make_float2(x0, x1);
            *(float2*)(C + (size_t)(row + 8) * ldc + col) = make_float2(x2, x3);
        }
    }
}

// ---------------- softmax (in place on energy buffer) ----------------
// att[b,h,l,:] = softmax( energy[b,h,l,:] * (1/sqrt(128)) * inter[b,0,l,:] )
__global__ void softmax_kernel(float* __restrict__ att, const float* __restrict__ inter)
{
    const float inv = 0.08838834764831845f;  // 1/sqrt(128)
    int idx = blockIdx.x;                    // (b*8+h)*256 + l
    int l = idx & (LL_ - 1);
    int b = idx >> 11;                       // / (H*LL)
    float* row = att + (size_t)idx * LP_;
    const float* irow = inter + ((size_t)b * LL_ + l) * LP_;
    int t = threadIdx.x;

    float v[4];
    float m = -3.402823466e38f;
#pragma unroll
    for (int i = 0; i < 4; i++) {
        int p = t + (i << 8);
        v[i] = row[p] * inv * irow[p];
        m = fmaxf(m, v[i]);
    }

    __shared__ float sm[8], ss[8];
#pragma unroll
    for (int o = 16; o; o >>= 1) m = fmaxf(m, __shfl_xor_sync(0xffffffffu, m, o));
    if ((t & 31) == 0) sm[t >> 5] = m;
    __syncthreads();
    m = sm[0];
#pragma unroll
    for (int w = 1; w < 8; w++) m = fmaxf(m, sm[w]);

    float s = 0.f;
#pragma unroll
    for (int i = 0; i < 4; i++) { v[i] = __expf(v[i] - m); s += v[i]; }
#pragma unroll
    for (int o = 16; o; o >>= 1) s += __shfl_xor_sync(0xffffffffu, s, o);
    if ((t & 31) == 0) ss[t >> 5] = s;
    __syncthreads();
    s = ss[0] + ss[1] + ss[2] + ss[3] + ss[4] + ss[5] + ss[6] + ss[7];
    float r = 1.0f / s;
#pragma unroll
    for (int i = 0; i < 4; i++) row[t + (i << 8)] = v[i] * r;
}

// ---------------- copy residual into concat buffer cols [128:256) ----------------
__global__ void copy_concat(const float4* __restrict__ src, float4* __restrict__ dst, int n4)
{
    int i = blockIdx.x * 256 + threadIdx.x;
    if (i < n4) {
        int r = i >> 5;
        int c = i & 31;
        dst[(size_t)r * 64 + 32 + c] = src[i];
    }
}

// ---------------- launcher ----------------
extern "C" void kernel_launch(void* const* d_in, const int* in_sizes, int n_in,
                              void* d_out, int out_size)
{
    const float* ligand = (const float*)d_in[0];
    const float* prot   = (const float*)d_in[1];
    const float* inter  = (const float*)d_in[2];
    const float* Wl1 = (const float*)d_in[3];  const float* bl1 = (const float*)d_in[4];
    const float* Wl2 = (const float*)d_in[5];  const float* bl2 = (const float*)d_in[6];
    const float* Wp1 = (const float*)d_in[7];  const float* bp1 = (const float*)d_in[8];
    const float* Wp2 = (const float*)d_in[9];  const float* bp2 = (const float*)d_in[10];
    const float* W11 = (const float*)d_in[11]; const float* b11 = (const float*)d_in[12];
    const float* W12 = (const float*)d_in[13]; const float* b12 = (const float*)d_in[14];
    const float* W21 = (const float*)d_in[15]; const float* b21 = (const float*)d_in[16];
    const float* W22 = (const float*)d_in[17]; const float* b22 = (const float*)d_in[18];

    float* out_lig  = (float*)d_out;                       // [16,256,128]
    float* out_prot = out_lig + (size_t)B_ * LL_ * HID_;   // [16,1024,128]

    float *l1, *l2, *p1, *p2, *att, *lig3, *prot3, *lcat, *pcat;
    cudaGetSymbolAddress((void**)&l1, g_l1);
    cudaGetSymbolAddress((void**)&l2, g_l2);
    cudaGetSymbolAddress((void**)&p1, g_p1);
    cudaGetSymbolAddress((void**)&p2, g_p2);
    cudaGetSymbolAddress((void**)&att, g_att);
    cudaGetSymbolAddress((void**)&lig3, g_lig3);
    cudaGetSymbolAddress((void**)&prot3, g_prot3);
    cudaGetSymbolAddress((void**)&lcat, g_ligcat);
    cudaGetSymbolAddress((void**)&pcat, g_protcat);

    dim3 blk(256);

    // --- projections: relu(x @ W + b) ---
    gemm_tc<128,128,16,false,false,true,true><<<dim3(8,32,1), blk>>>(
        ligand, Wl1, bl1, l1, 128, 128, 1024, 1024, 0,0,0,0,0,0);
    gemm_tc<128,128,16,false,false,true,true><<<dim3(8,32,1), blk>>>(
        ligand, Wl2, bl2, l2, 128, 128, 1024, 1024, 0,0,0,0,0,0);
    gemm_tc<128,128,16,false,false,true,true><<<dim3(8,128,1), blk>>>(
        prot, Wp1, bp1, p1, 128, 128, 1024, 1024, 0,0,0,0,0,0);
    gemm_tc<128,128,16,false,false,true,true><<<dim3(8,128,1), blk>>>(
        prot, Wp2, bp2, p2, 128, 128, 1024, 1024, 0,0,0,0,0,0);

    // --- energy[b,h] = l1_h @ p1_h^T : M=256, N=1024, K=128, TB ---
    gemm_tc<128,128,16,false,true,false,false><<<dim3(8,2,128), blk>>>(
        l1, p1, nullptr, att, 128, 1024, 1024, 1024,
        (long)LL_*HD_, 128, (long)LP_*HD_, 128,
        (long)H_*LL_*LP_, (long)LL_*LP_);

    // --- softmax (scale * inter gating), in place ---
    softmax_kernel<<<B_*H_*LL_, 256>>>(att, inter);

    // --- lig3[b,l,h*128+d] = att[b,h] @ p2_h : M=256, N=128, K=1024 ---
    gemm_tc<128,128,16,false,false,false,false><<<dim3(1,2,128), blk>>>(
        att, p2, nullptr, lig3, 1024, 1024, 1024, 1024,
        (long)H_*LL_*LP_, (long)LL_*LP_, (long)LP_*HD_, 128,
        (long)LL_*HD_, 128);

    // --- prot3[b,p,h*128+d] = att[b,h]^T @ l2_h : M=1024, N=128, K=256, TA ---
    gemm_tc<128,128,16,true,false,false,false><<<dim3(1,8,128), blk>>>(
        att, l2, nullptr, prot3, 256, 1024, 1024, 1024,
        (long)H_*LL_*LP_, (long)LL_*LP_, (long)LL_*HD_, 128,
        (long)LP_*HD_, 128);

    // --- ligand branch: cat(lig3@W11+b11, ligand) -> relu(@W12+b12) ---
    gemm_tc<128,128,16,false,false,true,false><<<dim3(1,32,1), blk>>>(
        lig3, W11, b11, lcat, 1024, 1024, 128, 256, 0,0,0,0,0,0);
    copy_concat<<<512, 256>>>((const float4*)ligand, (float4*)lcat, B_*LL_*32);
    gemm_tc<128,128,16,false,false,true,true><<<dim3(1,32,1), blk>>>(
        lcat, W12, b12, out_lig, 256, 256, 128, 128, 0,0,0,0,0,0);

    // --- protein branch: cat(prot3@W21+b21, prot) -> relu(@W22+b22) ---
    gemm_tc<128,128,16,false,false,true,false><<<dim3(1,128,1), blk>>>(
        prot3, W21, b21, pcat, 1024, 1024, 128, 256, 0,0,0,0,0,0);
    copy_concat<<<2048, 256>>>((const float4*)prot, (float4*)pcat, B_*LP_*32);
    gemm_tc<128,128,16,false,false,true,true><<<dim3(1,128,1), blk>>>(
        pcat, W22, b22, out_prot, 256, 256, 128, 128, 0,0,0,0,0,0);
}

// round 3
// speedup vs baseline: 4.1979x; 1.1084x over previous
#include <cuda_runtime.h>

#define B_    16
#define LL_   256
#define LP_   1024
#define HID_  128
#define H_    8
#define HD_   1024

// ---------------- scratch ----------------
__device__ float g_l1[B_ * LL_ * HD_];
__device__ float g_l2[B_ * LL_ * HD_];
__device__ float g_p1[B_ * LP_ * HD_];
__device__ float g_p2t[B_ * HD_ * LP_];                 // [b][h*128+d][p]
__device__ float g_att[(size_t)B_ * H_ * LL_ * LP_];
__device__ float g_lig3[B_ * LL_ * HD_];
__device__ float g_prot3[B_ * LP_ * HD_];
__device__ float g_ligcat[B_ * LL_ * 2 * HID_];
__device__ float g_protcat[B_ * LP_ * 2 * HID_];
__device__ float g_ligr[B_ * LL_ * HID_];
__device__ float g_protr[B_ * LP_ * HID_];
__device__ float g_w[851968];                           // transposed+rounded weights

// weight offsets in g_w
#define OW_L1  0
#define OW_L2  131072
#define OW_P1  262144
#define OW_P2  393216
#define OW_11  524288
#define OW_21  655360
#define OW_12  786432
#define OW_22  819200

// ---------------- helpers ----------------
__device__ __forceinline__ unsigned tf32_of(float f) {
    unsigned r;
    asm("cvt.rna.tf32.f32 %0, %1;" : "=r"(r) : "f"(f));
    return r;
}
__device__ __forceinline__ float tf32f(float f) { return __uint_as_float(tf32_of(f)); }

__device__ __forceinline__ void mma_tf32(float c[4], const unsigned a[4], const unsigned b[2]) {
    asm volatile(
        "mma.sync.aligned.m16n8k8.row.col.f32.tf32.tf32.f32 "
        "{%0,%1,%2,%3}, {%4,%5,%6,%7}, {%8,%9}, {%0,%1,%2,%3};"
        : "+f"(c[0]), "+f"(c[1]), "+f"(c[2]), "+f"(c[3])
        : "r"(a[0]), "r"(a[1]), "r"(a[2]), "r"(a[3]), "r"(b[0]), "r"(b[1]));
}

__device__ __forceinline__ void cp16(float* sm, const float* gm) {
    unsigned a = (unsigned)__cvta_generic_to_shared(sm);
    asm volatile("cp.async.cg.shared.global [%0], [%1], 16;" :: "r"(a), "l"(gm));
}
#define CP_COMMIT() asm volatile("cp.async.commit_group;" ::: "memory")
#define CP_WAIT2()  asm volatile("cp.async.wait_group 2;" ::: "memory")

// ================= cp.async TF32 GEMM (both operands k-major) =================
// C[M,N] = act(A @ B^T_layout + bias):  A [m][k] (lda), B [n][k] (ldb).
// Operands must already be tf32-rounded (HW truncation is then exact).
// CTA tile 128x128, BK=16, 3-stage cp.async pipeline, k-interleaved LDS.128 frags.
// BIASM: 0 none, 1 bias[col], 2 bias[row].
template<int ZH, int BIASM, bool RELU, bool ROUND>
__global__ __launch_bounds__(256, 2)
void gemm_cp(const float* __restrict__ Ag, const float* __restrict__ Bg,
             const float* __restrict__ bias, float* __restrict__ Cg,
             int K, int lda, int ldb, int ldc,
             long sAb, long sAh, long sBb, long sBh, long sCb, long sCh)
{
    extern __shared__ float sm[];   // 3 stages x (As 2048 + Bs 2048) floats = 48KB

    const int z  = blockIdx.z;
    const int zb = z / ZH, zh = z % ZH;
    const float* A = Ag + (size_t)zb * sAb + (size_t)zh * sAh;
    const float* B = Bg + (size_t)zb * sBb + (size_t)zh * sBh;
    float* C = Cg + (size_t)zb * sCb + (size_t)zh * sCh;

    const int tid  = threadIdx.x;
    const int lane = tid & 31, warp = tid >> 5;
    const int mw = warp & 1, nw = warp >> 1;
    const int g = lane >> 2, tg = lane & 3;
    const int bm = blockIdx.y * 128, bn = blockIdx.x * 128;

    // cp.async per-thread chunks: A/B each 512 x 16B chunks, 2 per thread
    const int r0 = tid >> 2,  kc = (tid & 3) << 2;
    const int r1 = r0 + 64;
    const float* gA0 = A + (size_t)(bm + r0) * lda + kc;
    const float* gA1 = A + (size_t)(bm + r1) * lda + kc;
    const float* gB0 = B + (size_t)(bn + r0) * ldb + kc;
    const float* gB1 = B + (size_t)(bn + r1) * ldb + kc;
    const int so = r0 * 16 + kc;          // smem float offset within tile
    const int s1 = r1 * 16 + kc;

    float acc[4][4][4];
#pragma unroll
    for (int i = 0; i < 4; i++)
#pragma unroll
        for (int j = 0; j < 4; j++)
#pragma unroll
            for (int r = 0; r < 4; r++) acc[i][j][r] = 0.f;

    const int nk = K >> 4;

    auto issue = [&](int t) {
        float* base = sm + (t % 3) * 4096;
        const size_t ko = (size_t)t << 4;
        cp16(base + so,        gA0 + ko);
        cp16(base + s1,        gA1 + ko);
        cp16(base + 2048 + so, gB0 + ko);
        cp16(base + 2048 + s1, gB1 + ko);
    };

    issue(0); CP_COMMIT();
    if (nk > 1) issue(1);
    CP_COMMIT();

    for (int t = 0; t < nk; t++) {
        if (t + 2 < nk) issue(t + 2);
        CP_COMMIT();
        CP_WAIT2();
        __syncthreads();

        const float* As = sm + (t % 3) * 4096;
        const float* Bs = As + 2048;

        float4 bf[4];
#pragma unroll
        for (int nt = 0; nt < 4; nt++)
            bf[nt] = *(const float4*)(Bs + (nw * 32 + nt * 8 + g) * 16 + 4 * tg);

#pragma unroll
        for (int mt = 0; mt < 4; mt++) {
            const int m0 = mw * 64 + mt * 16;
            float4 a0 = *(const float4*)(As + (m0 + g) * 16 + 4 * tg);
            float4 a1 = *(const float4*)(As + (m0 + g + 8) * 16 + 4 * tg);
            // k-interleave: mma0 covers phys k {4tg,4tg+1}, mma1 {4tg+2,4tg+3}
            unsigned af0[4] = {__float_as_uint(a0.x), __float_as_uint(a1.x),
                               __float_as_uint(a0.y), __float_as_uint(a1.y)};
            unsigned af1[4] = {__float_as_uint(a0.z), __float_as_uint(a1.z),
                               __float_as_uint(a0.w), __float_as_uint(a1.w)};
#pragma unroll
            for (int nt = 0; nt < 4; nt++) {
                unsigned b0[2] = {__float_as_uint(bf[nt].x), __float_as_uint(bf[nt].y)};
                mma_tf32(acc[mt][nt], af0, b0);
            }
#pragma unroll
            for (int nt = 0; nt < 4; nt++) {
                unsigned b1[2] = {__float_as_uint(bf[nt].z), __float_as_uint(bf[nt].w)};
                mma_tf32(acc[mt][nt], af1, b1);
            }
        }
        __syncthreads();
    }

    // epilogue
#pragma unroll
    for (int mt = 0; mt < 4; mt++) {
#pragma unroll
        for (int nt = 0; nt < 4; nt++) {
            int row = bm + mw * 64 + mt * 16 + g;
            int col = bn + nw * 32 + nt * 8 + 2 * tg;
            float x0 = acc[mt][nt][0], x1 = acc[mt][nt][1];
            float x2 = acc[mt][nt][2], x3 = acc[mt][nt][3];
            if (BIASM == 1) {
                float b0 = bias[col], b1 = bias[col + 1];
                x0 += b0; x1 += b1; x2 += b0; x3 += b1;
            } else if (BIASM == 2) {
                float br = bias[row], br8 = bias[row + 8];
                x0 += br; x1 += br; x2 += br8; x3 += br8;
            }
            if (RELU) {
                x0 = fmaxf(x0, 0.f); x1 = fmaxf(x1, 0.f);
                x2 = fmaxf(x2, 0.f); x3 = fmaxf(x3, 0.f);
            }
            if (ROUND) { x0 = tf32f(x0); x1 = tf32f(x1); x2 = tf32f(x2); x3 = tf32f(x3); }
            *(float2*)(C + (size_t)row * ldc + col) = make_float2(x0, x1);
            *(float2*)(C + (size_t)(row + 8) * ldc + col) = make_float2(x2, x3);
        }
    }
}

// ================= legacy register-staging GEMM (for att^T @ l2) =================
template <int BM, int BN, int BK, bool TA, bool TB, bool BIAS, bool RELU, bool ROUND>
__global__ __launch_bounds__(256, 2)
void gemm_tc(const float* __restrict__ Ag, const float* __restrict__ Bg,
             const float* __restrict__ bias, float* __restrict__ Cg,
             int K, int lda, int ldb, int ldc,
             long sAb, long sAh, long sBb, long sBh, long sCb, long sCh)
{
    __shared__ unsigned As[2][BK][BM + 8];
    __shared__ unsigned Bs[2][BK][BN + 8];

    const int z = blockIdx.z;
    const float* A = Ag + (size_t)(z >> 3) * sAb + (size_t)(z & 7) * sAh;
    const float* B = Bg + (size_t)(z >> 3) * sBb + (size_t)(z & 7) * sBh;
    float* C = Cg + (size_t)(z >> 3) * sCb + (size_t)(z & 7) * sCh;

    const int tid  = threadIdx.x;
    const int lane = tid & 31, warp = tid >> 5;
    const int mw = warp & 1, nw = warp >> 1;
    const int g = lane >> 2, tg = lane & 3;
    const int bm = blockIdx.y * BM, bn = blockIdx.x * BN;

    int aR[2], aC[2], bR[2], bC[2];
#pragma unroll
    for (int i = 0; i < 2; i++) {
        int idx = tid + i * 256;
        if (!TA) { aR[i] = idx / 4;  aC[i] = (idx % 4) * 4; }
        else     { aR[i] = idx / 32; aC[i] = (idx % 32) * 4; }
        if (!TB) { bR[i] = idx / 32; bC[i] = (idx % 32) * 4; }
        else     { bR[i] = idx / 4;  bC[i] = (idx % 4) * 4; }
    }

    float acc[4][4][4];
#pragma unroll
    for (int i = 0; i < 4; i++)
#pragma unroll
        for (int j = 0; j < 4; j++)
#pragma unroll
            for (int r = 0; r < 4; r++) acc[i][j][r] = 0.f;

    auto fetch = [&](int k0, float4* va, float4* vb) {
#pragma unroll
        for (int i = 0; i < 2; i++) {
            va[i] = TA ? *(const float4*)(A + (size_t)(k0 + aR[i]) * lda + bm + aC[i])
                       : *(const float4*)(A + (size_t)(bm + aR[i]) * lda + k0 + aC[i]);
            vb[i] = TB ? *(const float4*)(B + (size_t)(bn + bR[i]) * ldb + k0 + bC[i])
                       : *(const float4*)(B + (size_t)(k0 + bR[i]) * ldb + bn + bC[i]);
        }
    };
    auto stage = [&](int buf, const float4* va, const float4* vb) {
#pragma unroll
        for (int i = 0; i < 2; i++) {
            float fa[4] = {va[i].x, va[i].y, va[i].z, va[i].w};
            float fb[4] = {vb[i].x, vb[i].y, vb[i].z, vb[i].w};
            if (!TA) {
#pragma unroll
                for (int j = 0; j < 4; j++) As[buf][aC[i] + j][aR[i]] = tf32_of(fa[j]);
            } else {
#pragma unroll
                for (int j = 0; j < 4; j++) As[buf][aR[i]][aC[i] + j] = tf32_of(fa[j]);
            }
            if (!TB) {
#pragma unroll
                for (int j = 0; j < 4; j++) Bs[buf][bR[i]][bC[i] + j] = tf32_of(fb[j]);
            } else {
#pragma unroll
                for (int j = 0; j < 4; j++) Bs[buf][bC[i] + j][bR[i]] = tf32_of(fb[j]);
            }
        }
    };

    float4 va[2], vb[2];
    fetch(0, va, vb);
    stage(0, va, vb);
    __syncthreads();

    const int nk = K / BK;
    for (int t = 0; t < nk; t++) {
        const int buf = t & 1;
        float4 wa[2], wb[2];
        if (t + 1 < nk) fetch((t + 1) * BK, wa, wb);

#pragma unroll
        for (int ks = 0; ks < BK; ks += 8) {
            unsigned af[4][4], bf[4][2];
#pragma unroll
            for (int mt = 0; mt < 4; mt++) {
                int m0 = mw * 64 + mt * 16;
                af[mt][0] = As[buf][ks + tg][m0 + g];
                af[mt][1] = As[buf][ks + tg][m0 + g + 8];
                af[mt][2] = As[buf][ks + tg + 4][m0 + g];
                af[mt][3] = As[buf][ks + tg + 4][m0 + g + 8];
            }
#pragma unroll
            for (int nt = 0; nt < 4; nt++) {
                int n0 = nw * 32 + nt * 8;
                bf[nt][0] = Bs[buf][ks + tg][n0 + g];
                bf[nt][1] = Bs[buf][ks + tg + 4][n0 + g];
            }
#pragma unroll
            for (int mt = 0; mt < 4; mt++)
#pragma unroll
                for (int nt = 0; nt < 4; nt++)
                    mma_tf32(acc[mt][nt], af[mt], bf[nt]);
        }

        if (t + 1 < nk) stage(buf ^ 1, wa, wb);
        __syncthreads();
    }

#pragma unroll
    for (int mt = 0; mt < 4; mt++) {
#pragma unroll
        for (int nt = 0; nt < 4; nt++) {
            int row = bm + mw * 64 + mt * 16 + g;
            int col = bn + nw * 32 + nt * 8 + 2 * tg;
            float b0 = 0.f, b1 = 0.f;
            if (BIAS) { b0 = bias[col]; b1 = bias[col + 1]; }
            float x0 = acc[mt][nt][0] + b0;
            float x1 = acc[mt][nt][1] + b1;
            float x2 = acc[mt][nt][2] + b0;
            float x3 = acc[mt][nt][3] + b1;
            if (RELU) {
                x0 = fmaxf(x0, 0.f); x1 = fmaxf(x1, 0.f);
                x2 = fmaxf(x2, 0.f); x3 = fmaxf(x3, 0.f);
            }
            if (ROUND) { x0 = tf32f(x0); x1 = tf32f(x1); x2 = tf32f(x2); x3 = tf32f(x3); }
            *(float2*)(C + (size_t)row * ldc + col) = make_float2(x0, x1);
            *(float2*)(C + (size_t)(row + 8) * ldc + col) = make_float2(x2, x3);
        }
    }
}

// ---------------- pre-processing kernels ----------------
__global__ void round_inputs(const float4* __restrict__ lig, const float4* __restrict__ prot,
                             float4* __restrict__ ligr, float4* __restrict__ protr)
{
    int i = blockIdx.x * 256 + threadIdx.x;
    const int n1 = B_ * LL_ * HID_ / 4;
    const int n2 = B_ * LP_ * HID_ / 4;
    if (i < n1) {
        float4 v = lig[i];
        ligr[i] = make_float4(tf32f(v.x), tf32f(v.y), tf32f(v.z), tf32f(v.w));
    } else if (i < n1 + n2) {
        int j = i - n1;
        float4 v = prot[j];
        protr[j] = make_float4(tf32f(v.x), tf32f(v.y), tf32f(v.z), tf32f(v.w));
    }
}

// transpose+round all 8 weights into g_w (out[C][R] from in[R][C])
__global__ void transpose_round8(const float* w0, const float* w1, const float* w2,
                                 const float* w3, const float* w4, const float* w5,
                                 const float* w6, const float* w7, float* wb)
{
    const float* ins[8] = {w0, w1, w2, w3, w4, w5, w6, w7};
    const int Rs[8]   = {128, 128, 128, 128, 1024, 1024, 256, 256};
    const int Cs[8]   = {1024, 1024, 1024, 1024, 128, 128, 128, 128};
    const int offs[8] = {OW_L1, OW_L2, OW_P1, OW_P2, OW_11, OW_21, OW_12, OW_22};
    int zi = blockIdx.z;
    int R = Rs[zi], C = Cs[zi];
    int bx = blockIdx.x * 32, by = blockIdx.y * 32;
    if (bx >= C || by >= R) return;
    const float* in = ins[zi];
    float* out = wb + offs[zi];

    __shared__ float t[32][33];
    int tx = threadIdx.x, ty = threadIdx.y;
#pragma unroll
    for (int j = 0; j < 32; j += 8)
        t[ty + j][tx] = in[(size_t)(by + ty + j) * C + bx + tx];
    __syncthreads();
#pragma unroll
    for (int j = 0; j < 32; j += 8)
        out[(size_t)(bx + ty + j) * R + by + tx] = tf32f(t[tx][ty + j]);
}

// ---------------- softmax (in place, emits tf32-rounded att) ----------------
__global__ void softmax_kernel(float* __restrict__ att, const float* __restrict__ inter)
{
    const float inv = 0.08838834764831845f;
    int idx = blockIdx.x;
    int l = idx & (LL_ - 1);
    int b = idx >> 11;
    float* row = att + (size_t)idx * LP_;
    const float* irow = inter + ((size_t)b * LL_ + l) * LP_;
    int t = threadIdx.x;

    float v[4];
    float m = -3.402823466e38f;
#pragma unroll
    for (int i = 0; i < 4; i++) {
        int p = t + (i << 8);
        v[i] = row[p] * inv * irow[p];
        m = fmaxf(m, v[i]);
    }

    __shared__ float sm[8], ss[8];
#pragma unroll
    for (int o = 16; o; o >>= 1) m = fmaxf(m, __shfl_xor_sync(0xffffffffu, m, o));
    if ((t & 31) == 0) sm[t >> 5] = m;
    __syncthreads();
    m = sm[0];
#pragma unroll
    for (int w = 1; w < 8; w++) m = fmaxf(m, sm[w]);

    float s = 0.f;
#pragma unroll
    for (int i = 0; i < 4; i++) { v[i] = __expf(v[i] - m); s += v[i]; }
#pragma unroll
    for (int o = 16; o; o >>= 1) s += __shfl_xor_sync(0xffffffffu, s, o);
    if ((t & 31) == 0) ss[t >> 5] = s;
    __syncthreads();
    s = ss[0] + ss[1] + ss[2] + ss[3] + ss[4] + ss[5] + ss[6] + ss[7];
    float r = 1.0f / s;
#pragma unroll
    for (int i = 0; i < 4; i++) row[t + (i << 8)] = tf32f(v[i] * r);
}

// ---------------- residual concat copy ----------------
__global__ void copy_concat(const float4* __restrict__ src, float4* __restrict__ dst, int n4)
{
    int i = blockIdx.x * 256 + threadIdx.x;
    if (i < n4) {
        int r = i >> 5;
        int c = i & 31;
        dst[(size_t)r * 64 + 32 + c] = src[i];
    }
}

// ---------------- launcher ----------------
extern "C" void kernel_launch(void* const* d_in, const int* in_sizes, int n_in,
                              void* d_out, int out_size)
{
    const float* ligand = (const float*)d_in[0];
    const float* prot   = (const float*)d_in[1];
    const float* inter  = (const float*)d_in[2];
    const float* Wl1 = (const float*)d_in[3];  const float* bl1 = (const float*)d_in[4];
    const float* Wl2 = (const float*)d_in[5];  const float* bl2 = (const float*)d_in[6];
    const float* Wp1 = (const float*)d_in[7];  const float* bp1 = (const float*)d_in[8];
    const float* Wp2 = (const float*)d_in[9];  const float* bp2 = (const float*)d_in[10];
    const float* W11 = (const float*)d_in[11]; const float* b11 = (const float*)d_in[12];
    const float* W12 = (const float*)d_in[13]; const float* b12 = (const float*)d_in[14];
    const float* W21 = (const float*)d_in[15]; const float* b21 = (const float*)d_in[16];
    const float* W22 = (const float*)d_in[17]; const float* b22 = (const float*)d_in[18];

    float* out_lig  = (float*)d_out;
    float* out_prot = out_lig + (size_t)B_ * LL_ * HID_;

    float *l1, *l2, *p1, *p2t, *att, *lig3, *prot3, *lcat, *pcat, *ligr, *protr, *w;
    cudaGetSymbolAddress((void**)&l1, g_l1);
    cudaGetSymbolAddress((void**)&l2, g_l2);
    cudaGetSymbolAddress((void**)&p1, g_p1);
    cudaGetSymbolAddress((void**)&p2t, g_p2t);
    cudaGetSymbolAddress((void**)&att, g_att);
    cudaGetSymbolAddress((void**)&lig3, g_lig3);
    cudaGetSymbolAddress((void**)&prot3, g_prot3);
    cudaGetSymbolAddress((void**)&lcat, g_ligcat);
    cudaGetSymbolAddress((void**)&pcat, g_protcat);
    cudaGetSymbolAddress((void**)&ligr, g_ligr);
    cudaGetSymbolAddress((void**)&protr, g_protr);
    cudaGetSymbolAddress((void**)&w, g_w);

    dim3 blk(256);
    const int SMEM = 49152;

    // --- pre-round inputs + transpose/round weights ---
    round_inputs<<<2560, 256>>>((const float4*)ligand, (const float4*)prot,
                                (float4*)ligr, (float4*)protr);
    transpose_round8<<<dim3(32, 32, 8), dim3(32, 8)>>>(
        Wl1, Wl2, Wp1, Wp2, W11, W21, W12, W22, w);

    // --- projections ---
    gemm_cp<1,1,true,true><<<dim3(8,32,1), blk, SMEM>>>(
        ligr, w + OW_L1, bl1, l1, 128, 128, 128, 1024, 0,0,0,0,0,0);
    gemm_cp<1,1,true,true><<<dim3(8,32,1), blk, SMEM>>>(
        ligr, w + OW_L2, bl2, l2, 128, 128, 128, 1024, 0,0,0,0,0,0);
    gemm_cp<1,1,true,true><<<dim3(8,128,1), blk, SMEM>>>(
        protr, w + OW_P1, bp1, p1, 128, 128, 128, 1024, 0,0,0,0,0,0);
    // p2 transposed: p2t[b][hd][p] = relu(Wp2t @ protr_b^T + bp2[m])
    gemm_cp<1,2,true,true><<<dim3(8,8,16), blk, SMEM>>>(
        w + OW_P2, protr, bp2, p2t, 128, 128, 128, 1024,
        0, 0, (long)LP_*HID_, 0, (long)HD_*LP_, 0);

    // --- energy = l1 @ p1^T per (b,h) ---
    gemm_cp<8,0,false,false><<<dim3(8,2,128), blk, SMEM>>>(
        l1, p1, nullptr, att, 128, 1024, 1024, 1024,
        (long)LL_*HD_, 128, (long)LP_*HD_, 128,
        (long)H_*LL_*LP_, (long)LL_*LP_);

    softmax_kernel<<<B_*H_*LL_, 256>>>(att, inter);

    // --- lig3 = att @ p2  (B = p2t, k-major) ---
    gemm_cp<8,0,false,true><<<dim3(1,2,128), blk, SMEM>>>(
        att, p2t, nullptr, lig3, 1024, 1024, 1024, 1024,
        (long)H_*LL_*LP_, (long)LL_*LP_, (long)HD_*LP_, (long)128*LP_,
        (long)LL_*HD_, 128);

    // --- prot3 = att^T @ l2 (legacy path, TA) ---
    gemm_tc<128,128,16,true,false,false,false,true><<<dim3(1,8,128), blk>>>(
        att, l2, nullptr, prot3, 256, 1024, 1024, 1024,
        (long)H_*LL_*LP_, (long)LL_*LP_, (long)LL_*HD_, 128,
        (long)LP_*HD_, 128);

    // --- ligand branch ---
    gemm_cp<1,1,false,true><<<dim3(1,32,1), blk, SMEM>>>(
        lig3, w + OW_11, b11, lcat, 1024, 1024, 1024, 256, 0,0,0,0,0,0);
    copy_concat<<<512, 256>>>((const float4*)ligr, (float4*)lcat, B_*LL_*32);
    gemm_cp<1,1,true,false><<<dim3(1,32,1), blk, SMEM>>>(
        lcat, w + OW_12, b12, out_lig, 256, 256, 256, 128, 0,0,0,0,0,0);

    // --- protein branch ---
    gemm_cp<1,1,false,true><<<dim3(1,128,1), blk, SMEM>>>(
        prot3, w + OW_21, b21, pcat, 1024, 1024, 1024, 256, 0,0,0,0,0,0);
    copy_concat<<<2048, 256>>>((const float4*)protr, (float4*)pcat, B_*LP_*32);
    gemm_cp<1,1,true,false><<<dim3(1,128,1), blk, SMEM>>>(
        pcat, w + OW_22, b22, out_prot, 256, 256, 256, 128, 0,0,0,0,0,0);
}